// round 2
// baseline (speedup 1.0000x reference)
#include <cuda_runtime.h>

// ---------------------------------------------------------------------------
// FeatPropagation: k=3 NN (brute force per batch) + inverse-distance interp.
//
// CRITICAL: distance ranking must match the JAX reference BIT-EXACTLY.
// Reference computes d2 = q2 + s2 - 2*cross (GEMM form) in fp32:
//   q2 = (qx*qx + qy*qy) + qz*qz          (multiply + sequential reduce)
//   s2 = (px*px + py*py) + pz*pz
//   cross = fma(qz,pz, fma(qy,py, qx*px)) (GEMM K=3 fma accumulation)
//   d2 = (q2 + s2) - 2*cross  ==  fma(-2, cross, q2+s2)   (2*cross exact)
// All ops below use explicit-rounding intrinsics to forbid contraction.
//
// Phase 1 (knn_kernel): 1 thread/query; source tile in SMEM as float4
//   {x,y,z,s2} (one broadcast LDS.128 per candidate); top-3 in registers
//   with a group-min prefilter (insertions are rare: O(3 ln N) per thread).
// Phase 2 (interp_kernel): 1 thread per (query, float4 channel group).
// ---------------------------------------------------------------------------

#define CAP (1u << 18)          // >= 3 * total queries (3*65536 = 196608)
__device__ int   g_idx[CAP];
__device__ float g_w[CAP];

#define TILE      1024
#define KNN_BLOCK 128

__global__ void __launch_bounds__(KNN_BLOCK)
knn_kernel(const float* __restrict__ xyz, const float* __restrict__ qxyz,
           int N, int M)
{
    __shared__ float4 s4[TILE];   // {x, y, z, s2}

    const int  b      = blockIdx.y;
    const int  m      = blockIdx.x * KNN_BLOCK + threadIdx.x;
    const bool active = (m < M);
    const int  q      = b * M + m;

    float qx = 0.f, qy = 0.f, qz = 0.f, q2 = 0.f;
    if (active) {
        qx = qxyz[3 * q + 0];
        qy = qxyz[3 * q + 1];
        qz = qxyz[3 * q + 2];
        q2 = __fadd_rn(__fadd_rn(__fmul_rn(qx, qx), __fmul_rn(qy, qy)),
                       __fmul_rn(qz, qz));
    }

    // top-3 smallest d2 (sorted d0 <= d1 <= d2v)
    float d0 = 3.4e38f, d1 = 3.4e38f, d2v = 3.4e38f;
    int   i0 = 0, i1 = 0, i2 = 0;

    const float* src = xyz + (size_t)b * N * 3;

    // strict '<' + ascending scan == lowest-index tie-break (matches top_k)
    auto insert = [&](float dd, int s) {
        if (dd < d2v) {
            if (dd < d1) {
                d2v = d1; i2 = i1;
                if (dd < d0) { d1 = d0; i1 = i0; d0 = dd; i0 = s; }
                else         { d1 = dd; i1 = s; }
            } else {
                d2v = dd; i2 = s;
            }
        }
    };

    // d2 in the reference's exact arithmetic
    auto dist2 = [&](const float4& p) -> float {
        const float cross = __fmaf_rn(qz, p.z,
                             __fmaf_rn(qy, p.y, __fmul_rn(qx, p.x)));
        const float h = __fadd_rn(q2, p.w);          // q2 + s2
        return __fmaf_rn(-2.0f, cross, h);           // == (q2+s2) - 2*cross
    };

    for (int t0 = 0; t0 < N; t0 += TILE) {
        const int cnt = min(TILE, N - t0);

        for (int j = threadIdx.x; j < cnt; j += KNN_BLOCK) {
            const int s = (t0 + j) * 3;
            const float x = src[s + 0], y = src[s + 1], z = src[s + 2];
            const float s2 = __fadd_rn(__fadd_rn(__fmul_rn(x, x),
                                                 __fmul_rn(y, y)),
                                       __fmul_rn(z, z));
            s4[j] = make_float4(x, y, z, s2);
        }
        __syncthreads();

        if (active) {
            const int c4 = cnt & ~3;
            for (int j = 0; j < c4; j += 4) {
                const float4 p0 = s4[j + 0];
                const float4 p1 = s4[j + 1];
                const float4 p2 = s4[j + 2];
                const float4 p3 = s4[j + 3];

                const float dd0 = dist2(p0);
                const float dd1 = dist2(p1);
                const float dd2 = dist2(p2);
                const float dd3 = dist2(p3);

                const float gmin = fminf(fminf(dd0, dd1), fminf(dd2, dd3));
                if (gmin < d2v) {   // rare path: proper ordered insertions
                    insert(dd0, t0 + j + 0);
                    insert(dd1, t0 + j + 1);
                    insert(dd2, t0 + j + 2);
                    insert(dd3, t0 + j + 3);
                }
            }
            for (int j = c4; j < cnt; j++) {
                insert(dist2(s4[j]), t0 + j);
            }
        }
        __syncthreads();
    }

    if (active) {
        // match: dist = sqrt(max(d2, 1e-12)); w = (1/(dist+eps)) / sum
        const float e0 = sqrtf(fmaxf(d0,  1e-12f));
        const float e1 = sqrtf(fmaxf(d1,  1e-12f));
        const float e2 = sqrtf(fmaxf(d2v, 1e-12f));
        const float r0 = __fdiv_rn(1.0f, __fadd_rn(e0, 1e-8f));
        const float r1 = __fdiv_rn(1.0f, __fadd_rn(e1, 1e-8f));
        const float r2 = __fdiv_rn(1.0f, __fadd_rn(e2, 1e-8f));
        const float s  = __fadd_rn(__fadd_rn(r0, r1), r2);

        const int base  = 3 * q;
        g_idx[base + 0] = b * N + i0;
        g_idx[base + 1] = b * N + i1;
        g_idx[base + 2] = b * N + i2;
        g_w[base + 0]   = __fdiv_rn(r0, s);
        g_w[base + 1]   = __fdiv_rn(r1, s);
        g_w[base + 2]   = __fdiv_rn(r2, s);
    }
}

__global__ void __launch_bounds__(256)
interp_kernel(const float* __restrict__ feat, float* __restrict__ out,
              int C4, int total)
{
    const int t = blockIdx.x * 256 + threadIdx.x;
    if (t >= total) return;

    const int q  = t / C4;
    const int cg = t - q * C4;

    const int   base = 3 * q;
    const int   i0 = g_idx[base + 0];
    const int   i1 = g_idx[base + 1];
    const int   i2 = g_idx[base + 2];
    const float w0 = g_w[base + 0];
    const float w1 = g_w[base + 1];
    const float w2 = g_w[base + 2];

    const float4* f = reinterpret_cast<const float4*>(feat);
    const float4 a = __ldg(f + (size_t)i0 * C4 + cg);
    const float4 b = __ldg(f + (size_t)i1 * C4 + cg);
    const float4 c = __ldg(f + (size_t)i2 * C4 + cg);

    float4 o;
    o.x = fmaf(w2, c.x, fmaf(w1, b.x, w0 * a.x));
    o.y = fmaf(w2, c.y, fmaf(w1, b.y, w0 * a.y));
    o.z = fmaf(w2, c.z, fmaf(w1, b.z, w0 * a.z));
    o.w = fmaf(w2, c.w, fmaf(w1, b.w, w0 * a.w));

    reinterpret_cast<float4*>(out)[t] = o;
}

extern "C" void kernel_launch(void* const* d_in, const int* in_sizes, int n_in,
                              void* d_out, int out_size)
{
    const float* xyz     = (const float*)d_in[0];
    const float* new_xyz = (const float*)d_in[1];
    const float* feat    = (const float*)d_in[2];

    const int B    = in_sizes[3];           // offset element count == batch count
    const int Ntot = in_sizes[0] / 3;
    const int Mtot = in_sizes[1] / 3;
    const int N    = Ntot / B;
    const int M    = Mtot / B;
    const int C    = in_sizes[2] / Ntot;

    // Phase 1: kNN + weights
    dim3 g1((M + KNN_BLOCK - 1) / KNN_BLOCK, B);
    knn_kernel<<<g1, KNN_BLOCK>>>(xyz, new_xyz, N, M);

    // Phase 2: weighted feature gather
    const int C4    = C / 4;                // C = 256 -> 64 float4 groups
    const int total = Mtot * C4;
    interp_kernel<<<(total + 255) / 256, 256>>>(feat, (float*)d_out, C4, total);
}